// round 15
// baseline (speedup 1.0000x reference)
#include <cuda_runtime.h>
#include <cstdint>

// Fused conv3x3-VALID + bias + mish + BN(inference), implicit GEMM on
// mma.sync m16n8k32 s8 (int8 split-2: x,w -> int16 -> hi/lo int8 pairs).
// D = [65536*XhWh + 256*(XhWl+XlWh)] / (Sx*Sw); XlWl dropped (~4e-4 rel).
// Per CTA: ONE (n,h) output row x 64 oc. 256 threads / 8 warps, 2 CTAs/SM.
// Warp tile 32 px x 32 oc; B per kh-group (3 taps), 3 barrier intervals.

#define HIN   128
#define WIN   128
#define CINC  64
#define COUTC 128
#define HOUTC 126
#define WOUTC 126
#define NBATCH 32

#define SX 4096.0f
#define SW 65536.0f
#define INV_SS 3.7252902984619141e-9f   // 2^-28 = 1/(SX*SW), exact in fp32

__device__ __align__(16) signed char g_x8h[NBATCH * HIN * WIN * CINC];  // NHWC hi
__device__ __align__(16) signed char g_x8l[NBATCH * HIN * WIN * CINC];  // NHWC lo
__device__ __align__(16) signed char g_w8h[9 * COUTC * CINC];           // [tap][oc][ic]
__device__ __align__(16) signed char g_w8l[9 * COUTC * CINC];

__device__ __forceinline__ uint32_t smem_u32(const void* p) {
    uint32_t a;
    asm("{ .reg .u64 t; cvta.to.shared.u64 t, %1; cvt.u32.u64 %0, t; }" : "=r"(a) : "l"(p));
    return a;
}
// SW64 swizzle for 64-byte rows (8 rows x 64B atom): toggles 16B-chunk bits
#define SW64(o) ((o) ^ (((o) >> 3) & 0x30))

#define CP_ASYNC16(dst, src) \
    asm volatile("cp.async.cg.shared.global [%0], [%1], 16;" :: "r"(dst), "l"(src) : "memory")
#define CP_COMMIT() asm volatile("cp.async.commit_group;" ::: "memory")
#define CP_WAIT0()  asm volatile("cp.async.wait_group 0;" ::: "memory")

__device__ __forceinline__ void ldsm_x4(uint32_t addr, uint32_t* r) {
    asm volatile("ldmatrix.sync.aligned.m8n8.x4.shared.b16 {%0,%1,%2,%3}, [%4];"
        : "=r"(r[0]), "=r"(r[1]), "=r"(r[2]), "=r"(r[3]) : "r"(addr));
}
__device__ __forceinline__ void mma_s8(int* d, const uint32_t* a,
                                       uint32_t b0, uint32_t b1) {
    asm volatile("mma.sync.aligned.m16n8k32.row.col.s32.s8.s8.s32 "
        "{%0,%1,%2,%3}, {%4,%5,%6,%7}, {%8,%9}, {%0,%1,%2,%3};"
        : "+r"(d[0]), "+r"(d[1]), "+r"(d[2]), "+r"(d[3])
        : "r"(a[0]), "r"(a[1]), "r"(a[2]), "r"(a[3]), "r"(b0), "r"(b1));
}

// split signed int16-range value into int8 hi/lo: v = 256*hi + lo, lo in [-128,127]
__device__ __forceinline__ void split16(int v, signed char& hi, signed char& lo) {
    int l = (int)(signed char)(v & 0xFF);
    hi = (signed char)((v - l) >> 8);
    lo = (signed char)l;
}

// ---------------- prepass: weights OIHW fp32 -> [tap][oc][ic] s8 hi/lo ----
__global__ void wprep_kernel(const float* __restrict__ wgt) {
    int i = blockIdx.x * 256 + threadIdx.x;
    if (i >= 9 * COUTC * CINC) return;
    int oc = i / (9 * CINC);
    int j  = i - oc * (9 * CINC);
    int t  = j >> 6;
    int ic = j & 63;
    int v = __float2int_rn(wgt[oc * 576 + ic * 9 + t] * SW);
    signed char hi, lo;
    split16(v, hi, lo);
    g_w8h[(t * COUTC + oc) * CINC + ic] = hi;
    g_w8l[(t * COUTC + oc) * CINC + ic] = lo;
}

// ---------------- prepass: x NCHW fp32 -> NHWC s8 hi/lo ----------------
__global__ void xprep_kernel(const float* __restrict__ x) {
    __shared__ float s[CINC][129];   // pad 129: write conflict-free, read 2-way
    const int h = blockIdx.x, n = blockIdx.y, tid = threadIdx.x;
    const float* xrow = x + (((size_t)n * CINC) * HIN + h) * WIN;
    for (int i = tid; i < CINC * WIN; i += 256) {
        const int ic = i >> 7, w = i & 127;
        s[ic][w] = xrow[(size_t)ic * (HIN * WIN) + w];
    }
    __syncthreads();
    const int outbase = ((n * HIN + h) * WIN) * CINC;
    for (int j = tid; j < WIN * 8; j += 256) {
        int w = j >> 3, icg = j & 7;
        __align__(8) signed char h8[8], l8[8];
#pragma unroll
        for (int u = 0; u < 8; u++) {
            int v = __float2int_rn(s[icg * 8 + u][w] * SX);
            split16(v, h8[u], l8[u]);
        }
        *(uint2*)(g_x8h + outbase + w * CINC + icg * 8) = *(uint2*)h8;
        *(uint2*)(g_x8l + outbase + w * CINC + icg * 8) = *(uint2*)l8;
    }
}

// ---------------- main kernel ----------------
// smem: params(2048)
//  | A: hi 3x8KB then lo 3x8KB (rows h..h+2, 128 px x 64B, SW64)
//  | B: 2 x 24KB groups (3 taps x [hi 4KB | lo 4KB])
#define SM_PAR 0
#define SM_A   2048
#define SM_B   (SM_A + 6 * 8192)       // 51200
#define BGRP   24576
#define SMEM_TOTAL (SM_B + 2 * BGRP)   // 100352 -> 2 CTAs/SM

__device__ __forceinline__ void load_b_group(uint32_t sbase, int g, int ocb,
                                             int buf, int tid) {
#pragma unroll
    for (int k = 0; k < 6; k++) {
        const int idx = tid + k * 256;        // 0..1535
        const int kw   = idx >> 9;            // tap in group
        const int wit  = idx & 511;
        const int part = wit >> 8;            // 0 hi, 1 lo
        const int w2   = wit & 255;
        const int r = w2 >> 2, c = w2 & 3;    // oc local 0..63, 16B chunk 0..3
        const signed char* src = (part ? g_w8l : g_w8h) +
            ((g * 3 + kw) * COUTC + ocb + r) * CINC + c * 16;
        const uint32_t dst = sbase + SM_B + buf * BGRP + kw * 8192 + part * 4096 +
                             SW64((uint32_t)(r * 64 + c * 16));
        CP_ASYNC16(dst, src);
    }
}

__global__ __launch_bounds__(256, 2)
void conv_imma_kernel(const float* __restrict__ bias,
                      const float* __restrict__ gamma,
                      const float* __restrict__ beta,
                      const float* __restrict__ rmean,
                      const float* __restrict__ rvar,
                      float* __restrict__ out)
{
    extern __shared__ char smem[];
    const uint32_t sbase = smem_u32(smem);
    const int tid = threadIdx.x, lane = tid & 31, wid = tid >> 5;
    const int h   = blockIdx.x;
    const int ocb = blockIdx.y * 64;
    const int n   = blockIdx.z;

    if (tid < 64) {
        const int oc = ocb + tid;
        const float sc = gamma[oc] * rsqrtf(rvar[oc] + 1e-5f);
        ((float*)(smem + SM_PAR))[tid]       = bias[oc];
        ((float*)(smem + SM_PAR + 256))[tid] = sc;
        ((float*)(smem + SM_PAR + 512))[tid] = beta[oc] - rmean[oc] * sc;
    }

    // --- stage A: 3 input rows, hi+lo, SW64, cp.async (48 KB = 12 chunks/thr)
#pragma unroll
    for (int k = 0; k < 12; k++) {
        const int idx = tid + k * 256;        // 0..3071
        const int part = idx / 1536;          // 0 hi, 1 lo
        const int within = idx - part * 1536;
        const int rowt = within >> 9;         // input row 0..2
        const int wit  = within & 511;
        const int r = wit >> 2, c = wit & 3;  // px 0..127, 16B chunk 0..3
        const signed char* src = (part ? g_x8l : g_x8h) +
            (((n * HIN + (h + rowt)) * WIN) + r) * CINC + c * 16;
        const uint32_t dst = sbase + SM_A + part * 24576 + rowt * 8192 +
                             SW64((uint32_t)(r * 64 + c * 16));
        CP_ASYNC16(dst, src);
    }
    // --- stage B group 0 ---
    load_b_group(sbase, 0, ocb, 0, tid);
    CP_COMMIT();
    CP_WAIT0();
    __syncthreads();

    // warp tile: 32 px x 32 oc
    const int mw = (wid & 3) * 32;      // pixel base
    const int n0 = (wid >> 2) * 32;     // oc base within 64-oc half
    const int quad = lane >> 3;

    int hh[2][4][4], mid[2][4][4];
#pragma unroll
    for (int i = 0; i < 2; i++)
#pragma unroll
        for (int j = 0; j < 4; j++)
#pragma unroll
            for (int e = 0; e < 4; e++) { hh[i][j][e] = 0; mid[i][j][e] = 0; }

    for (int kh = 0; kh < 3; kh++) {
        const int b = kh & 1;
        if (kh < 2) {
            load_b_group(sbase, kh + 1, ocb, b ^ 1, tid);
            CP_COMMIT();
        }

        const uint32_t aHi = sbase + SM_A + kh * 8192;
        const uint32_t aLo = aHi + 24576;
        const uint32_t bG  = sbase + SM_B + b * BGRP;

#pragma unroll
        for (int kw = 0; kw < 3; kw++) {
            const uint32_t bHi = bG + kw * 8192;
            const uint32_t bLo = bHi + 4096;
#pragma unroll
            for (int ks = 0; ks < 2; ks++) {   // 2 x k32 covers 64 ic
                uint32_t ah[2][4], al[2][4];
#pragma unroll
                for (int i = 0; i < 2; i++) {
                    // row can exceed 127 for kw>0 at mw=96: reads spill into the
                    // next smem tile; they feed only discarded outputs (w>=126).
                    const int row = mw + i * 16 + (lane & 15) + kw;
                    const uint32_t off =
                        SW64((uint32_t)(row * 64 + ks * 32 + (lane >> 4) * 16));
                    ldsm_x4(aHi + off, ah[i]);
                    ldsm_x4(aLo + off, al[i]);
                }
#pragma unroll
                for (int jj = 0; jj < 2; jj++) {
                    const int brow = n0 + jj * 16 + (quad >> 1) * 8 + (lane & 7);
                    const uint32_t boff =
                        SW64((uint32_t)(brow * 64 + ks * 32 + (quad & 1) * 16));
                    uint32_t bh[4], bl[4];
                    ldsm_x4(bHi + boff, bh);
                    ldsm_x4(bLo + boff, bl);
#pragma unroll
                    for (int i = 0; i < 2; i++) {
                        mma_s8(hh[i][jj * 2],      ah[i], bh[0], bh[1]);
                        mma_s8(hh[i][jj * 2 + 1],  ah[i], bh[2], bh[3]);
                        mma_s8(mid[i][jj * 2],     ah[i], bl[0], bl[1]);
                        mma_s8(mid[i][jj * 2 + 1], ah[i], bl[2], bl[3]);
                        mma_s8(mid[i][jj * 2],     al[i], bh[0], bh[1]);
                        mma_s8(mid[i][jj * 2 + 1], al[i], bh[2], bh[3]);
                    }
                }
            }
        }

        if (kh < 2) { CP_WAIT0(); __syncthreads(); }
    }

    // --- epilogue: combine int accs, bias + mish + BN ---
    const float* s_bias  = (const float*)(smem + SM_PAR);
    const float* s_scale = (const float*)(smem + SM_PAR + 256);
    const float* s_shift = (const float*)(smem + SM_PAR + 512);

#pragma unroll
    for (int i = 0; i < 2; i++)
#pragma unroll
        for (int j = 0; j < 4; j++)
#pragma unroll
            for (int e = 0; e < 4; e++) {
                const int w   = mw + i * 16 + (lane >> 2) + ((e & 2) ? 8 : 0);
                const int ocl = n0 + j * 8 + (lane & 3) * 2 + (e & 1);
                if (w < WOUTC) {
                    const float conv =
                        fmaf((float)hh[i][j][e], 65536.0f,
                             (float)mid[i][j][e] * 256.0f) * INV_SS;
                    const float z = conv + s_bias[ocl];
                    // mish: z*tanh(softplus(z)) = z*v/(v+2), v = e^z*(e^z+2);
                    // clamp: z>=30 -> v/(v+2)==1.0f in fp32 -> m==z exactly.
                    const float zc = fminf(z, 30.0f);
                    float u;
                    asm("ex2.approx.f32 %0, %1;" : "=f"(u) : "f"(zc * 1.44269504f));
                    const float v = u * (u + 2.0f);
                    const float m = z * __fdividef(v, v + 2.0f);
                    out[(((size_t)n * COUTC + (ocb + ocl)) * HOUTC + h) * WOUTC + w] =
                        fmaf(m, s_scale[ocl], s_shift[ocl]);
                }
            }
}

// ---------------- launch ----------------
extern "C" void kernel_launch(void* const* d_in, const int* in_sizes, int n_in,
                              void* d_out, int out_size)
{
    const float* x     = (const float*)d_in[0];
    const float* wgt   = (const float*)d_in[1];
    const float* bias  = (const float*)d_in[2];
    const float* gamma = (const float*)d_in[3];
    const float* beta  = (const float*)d_in[4];
    const float* rmean = (const float*)d_in[5];
    const float* rvar  = (const float*)d_in[6];
    float* out = (float*)d_out;

    cudaFuncSetAttribute(conv_imma_kernel,
                         cudaFuncAttributeMaxDynamicSharedMemorySize, SMEM_TOTAL);

    wprep_kernel<<<(9 * COUTC * CINC + 255) / 256, 256>>>(wgt);
    xprep_kernel<<<dim3(HIN, NBATCH), 256>>>(x);
    conv_imma_kernel<<<dim3(HOUTC, 2, NBATCH), 256, SMEM_TOTAL>>>(bias, gamma, beta,
                                                                  rmean, rvar, out);
}

// round 16
// speedup vs baseline: 6.0637x; 6.0637x over previous
#include <cuda_runtime.h>
#include <cuda_fp16.h>
#include <cstdint>

// Fused conv3x3-VALID + bias + mish + BN(inference), implicit GEMM on
// mma.sync m16n8k16 fp16 (x and weights fp16; rel_err ~3e-4 < 1e-3).
// Per CTA: ONE (n,h) output row x 64 oc. 256 threads / 8 warps, 2 CTAs/SM.
// Warp tile 32 px x 32 oc. B loaded per kh-group (3 taps = 24 KB), 3 barriers.
// R16: single merged prep kernel (weights folded into the x-transpose pass).

#define HIN   128
#define WIN   128
#define CINC  64
#define COUTC 128
#define HOUTC 126
#define WOUTC 126
#define NBATCH 32

__device__ __align__(16) __half g_xh[NBATCH * HIN * WIN * CINC];  // NHWC fp16
__device__ __align__(16) __half g_bh[9 * COUTC * CINC];           // [tap][oc][ic]

__device__ __forceinline__ uint32_t smem_u32(const void* p) {
    uint32_t a;
    asm("{ .reg .u64 t; cvta.to.shared.u64 t, %1; cvt.u32.u64 %0, t; }" : "=r"(a) : "l"(p));
    return a;
}
#define SW128(o) ((o) ^ (((o) >> 3) & 0x70))

#define CP_ASYNC16(dst, src) \
    asm volatile("cp.async.cg.shared.global [%0], [%1], 16;" :: "r"(dst), "l"(src) : "memory")
#define CP_COMMIT() asm volatile("cp.async.commit_group;" ::: "memory")
#define CP_WAIT0()  asm volatile("cp.async.wait_group 0;" ::: "memory")

__device__ __forceinline__ void ldsm_x4(uint32_t addr, uint32_t* r) {
    asm volatile("ldmatrix.sync.aligned.m8n8.x4.shared.b16 {%0,%1,%2,%3}, [%4];"
        : "=r"(r[0]), "=r"(r[1]), "=r"(r[2]), "=r"(r[3]) : "r"(addr));
}
__device__ __forceinline__ void mma_fp16(float* d, const uint32_t* a,
                                         uint32_t b0, uint32_t b1) {
    asm volatile("mma.sync.aligned.m16n8k16.row.col.f32.f16.f16.f32 "
        "{%0,%1,%2,%3}, {%4,%5,%6,%7}, {%8,%9}, {%0,%1,%2,%3};"
        : "+f"(d[0]), "+f"(d[1]), "+f"(d[2]), "+f"(d[3])
        : "r"(a[0]), "r"(a[1]), "r"(a[2]), "r"(a[3]), "r"(b0), "r"(b1));
}

// ---------------- merged prepass ----------------
// x: NCHW fp32 -> NHWC fp16 (one block per (h, n) row, 256 threads)
// w: OIHW fp32 -> [tap][oc][ic] fp16 (18 elements folded into each block)
__global__ void prep_kernel(const float* __restrict__ x,
                            const float* __restrict__ wgt) {
    __shared__ float s[CINC][129];   // pad 129: write conflict-free, read 2-way
    const int h = blockIdx.x, n = blockIdx.y, tid = threadIdx.x;

    // --- weight slice: 4096 blocks x 18 elements = 73728 exactly ---
    if (tid < 18) {
        const int i  = (n * HIN + h) * 18 + tid;
        const int oc = i / (9 * CINC);
        const int j  = i - oc * (9 * CINC);
        const int t  = j >> 6;
        const int ic = j & 63;
        g_bh[(t * COUTC + oc) * CINC + ic] = __float2half(wgt[oc * 576 + ic * 9 + t]);
    }

    // --- x transpose+convert for this (n, h) row ---
    const float* xrow = x + (((size_t)n * CINC) * HIN + h) * WIN;
    for (int i = tid; i < CINC * WIN; i += 256) {
        const int ic = i >> 7, w = i & 127;     // lane varies w -> coalesced
        s[ic][w] = xrow[(size_t)ic * (HIN * WIN) + w];
    }
    __syncthreads();
    const int outbase = ((n * HIN + h) * WIN) * CINC;
    for (int j = tid; j < WIN * 8; j += 256) {
        int w = j >> 3, icg = j & 7;
        __align__(16) __half h8[8];
#pragma unroll
        for (int u = 0; u < 8; u++) h8[u] = __float2half(s[icg * 8 + u][w]);
        *(uint4*)(g_xh + outbase + w * CINC + icg * 8) = *(uint4*)h8;
    }
}

// ---------------- main kernel (frozen from R13/R14 best) ----------------
// smem: params(2048) | A: 3 x 16KB (rows h..h+2) | B: 2 x 24KB (3-tap groups, 64 oc)
#define SM_PAR 0
#define SM_A   2048
#define SM_B   (SM_A + 3 * 16384)
#define BGRP   24576
#define SMEM_TOTAL (SM_B + 2 * BGRP)   // 98 KB -> 2 CTAs/SM

// load one kh group: taps 3*g..3*g+2 for this CTA's 64-oc half (24 KB)
__device__ __forceinline__ void load_b_group(uint32_t sbase, int g, int ocb,
                                             int buf, int tid) {
#pragma unroll
    for (int k = 0; k < 6; k++) {
        const int idx = tid + k * 256;        // 0..1535
        const int kw  = idx / 512;            // tap within group (512 chunks/tap)
        const int wit = idx - kw * 512;
        const int r = wit >> 3, c = wit & 7;  // oc local 0..63, 16B chunk 0..7
        const __half* src = g_bh + ((g * 3 + kw) * COUTC + ocb + r) * CINC + c * 8;
        const uint32_t dst = sbase + SM_B + buf * BGRP + kw * 8192 +
                             SW128((uint32_t)(r * 128 + c * 16));
        CP_ASYNC16(dst, src);
    }
}

__global__ __launch_bounds__(256, 2)
void conv_hmma_kernel(const float* __restrict__ bias,
                      const float* __restrict__ gamma,
                      const float* __restrict__ beta,
                      const float* __restrict__ rmean,
                      const float* __restrict__ rvar,
                      float* __restrict__ out)
{
    extern __shared__ char smem[];
    const uint32_t sbase = smem_u32(smem);
    const int tid = threadIdx.x, lane = tid & 31, wid = tid >> 5;
    const int h   = blockIdx.x;
    const int ocb = blockIdx.y * 64;          // oc half base
    const int n   = blockIdx.z;

    if (tid < 64) {
        const int oc = ocb + tid;
        const float sc = gamma[oc] * rsqrtf(rvar[oc] + 1e-5f);
        ((float*)(smem + SM_PAR))[tid]       = bias[oc];
        ((float*)(smem + SM_PAR + 256))[tid] = sc;
        ((float*)(smem + SM_PAR + 512))[tid] = beta[oc] - rmean[oc] * sc;
    }

    // --- stage A: 3 input rows (h..h+2), SW128, cp.async ---
#pragma unroll
    for (int k = 0; k < 12; k++) {
        const int idx  = tid + k * 256;       // 0..3071
        const int tile = idx >> 10;           // input row 0..2
        const int wit  = idx & 1023;
        const int r = wit >> 3, c = wit & 7;  // pixel w, 16B chunk
        const __half* src = g_xh + (((n * HIN + (h + tile)) * WIN) + r) * CINC + c * 8;
        const uint32_t dst = sbase + SM_A + tile * 16384 +
                             SW128((uint32_t)(r * 128 + c * 16));
        CP_ASYNC16(dst, src);
    }
    // --- stage B group 0 (taps 0..2) ---
    load_b_group(sbase, 0, ocb, 0, tid);
    CP_COMMIT();
    CP_WAIT0();
    __syncthreads();

    // warp tile: 32 px x 32 oc
    const int mw = (wid & 3) * 32;      // pixel base
    const int n0 = (wid >> 2) * 32;     // oc base within the 64-oc half

    float acc[2][4][4];
#pragma unroll
    for (int i = 0; i < 2; i++)
#pragma unroll
        for (int j = 0; j < 4; j++)
#pragma unroll
            for (int e = 0; e < 4; e++) acc[i][j][e] = 0.0f;

    for (int kh = 0; kh < 3; kh++) {
        const int b = kh & 1;
        if (kh < 2) {   // prefetch next kh group into other buffer
            load_b_group(sbase, kh + 1, ocb, b ^ 1, tid);
            CP_COMMIT();
        }

        const uint32_t aT = sbase + SM_A + kh * 16384;
        const uint32_t bG = sbase + SM_B + b * BGRP;

#pragma unroll
        for (int kw = 0; kw < 3; kw++) {
            const uint32_t bT = bG + kw * 8192;
#pragma unroll
            for (int ks = 0; ks < 4; ks++) {
                uint32_t ah[2][4];
#pragma unroll
                for (int i = 0; i < 2; i++) {
                    // row can exceed 127 for kw>0 at mw=96: spills into adjacent
                    // smem, feeds only discarded outputs (w>=126). Finite fp16.
                    const int row = mw + i * 16 + (lane & 15) + kw;
                    const uint32_t off =
                        SW128((uint32_t)(row * 128 + (ks * 2 + (lane >> 4)) * 16));
                    ldsm_x4(aT + off, ah[i]);
                }
#pragma unroll
                for (int jj = 0; jj < 2; jj++) {
                    const int quad = lane >> 3;
                    const int brow = n0 + jj * 16 + (quad >> 1) * 8 + (lane & 7);
                    const uint32_t boff =
                        SW128((uint32_t)(brow * 128 + (ks * 2 + (quad & 1)) * 16));
                    uint32_t bf[4];
                    ldsm_x4(bT + boff, bf);
#pragma unroll
                    for (int i = 0; i < 2; i++) {
                        mma_fp16(acc[i][jj * 2],     ah[i], bf[0], bf[1]);
                        mma_fp16(acc[i][jj * 2 + 1], ah[i], bf[2], bf[3]);
                    }
                }
            }
        }

        if (kh < 2) { CP_WAIT0(); __syncthreads(); }
    }

    // --- epilogue: bias + mish + BN (branchless large-z via input clamp) ---
    const float* s_bias  = (const float*)(smem + SM_PAR);
    const float* s_scale = (const float*)(smem + SM_PAR + 256);
    const float* s_shift = (const float*)(smem + SM_PAR + 512);

#pragma unroll
    for (int i = 0; i < 2; i++)
#pragma unroll
        for (int j = 0; j < 4; j++)
#pragma unroll
            for (int e = 0; e < 4; e++) {
                const int w   = mw + i * 16 + (lane >> 2) + ((e & 2) ? 8 : 0);
                const int ocl = n0 + j * 8 + (lane & 3) * 2 + (e & 1);
                if (w < WOUTC) {
                    const float z = acc[i][j][e] + s_bias[ocl];
                    // mish: z*tanh(softplus(z)) = z*v/(v+2), v = e^z*(e^z+2).
                    // clamp: for z>=30, v/(v+2)==1.0f in fp32 -> m==z exactly.
                    const float zc = fminf(z, 30.0f);
                    float u;
                    asm("ex2.approx.f32 %0, %1;" : "=f"(u) : "f"(zc * 1.44269504f));
                    const float v = u * (u + 2.0f);
                    const float m = z * __fdividef(v, v + 2.0f);
                    out[(((size_t)n * COUTC + (ocb + ocl)) * HOUTC + h) * WOUTC + w] =
                        fmaf(m, s_scale[ocl], s_shift[ocl]);
                }
            }
}

// ---------------- launch ----------------
extern "C" void kernel_launch(void* const* d_in, const int* in_sizes, int n_in,
                              void* d_out, int out_size)
{
    const float* x     = (const float*)d_in[0];
    const float* wgt   = (const float*)d_in[1];
    const float* bias  = (const float*)d_in[2];
    const float* gamma = (const float*)d_in[3];
    const float* beta  = (const float*)d_in[4];
    const float* rmean = (const float*)d_in[5];
    const float* rvar  = (const float*)d_in[6];
    float* out = (float*)d_out;

    cudaFuncSetAttribute(conv_hmma_kernel,
                         cudaFuncAttributeMaxDynamicSharedMemorySize, SMEM_TOTAL);

    prep_kernel<<<dim3(HIN, NBATCH), 256>>>(x, wgt);
    conv_hmma_kernel<<<dim3(HOUTC, 2, NBATCH), 256, SMEM_TOTAL>>>(bias, gamma, beta,
                                                                  rmean, rvar, out);
}